// round 1
// baseline (speedup 1.0000x reference)
#include <cuda_runtime.h>
#include <math.h>

#define B_   4
#define S_   256
#define V_   64
#define LP1_ 11
#define H_   128
#define NH_  8
#define DH_  16
#define NL_  3
#define M_   (B_*S_)   // 1024

// ---------------- scratch (device globals; no allocation) ----------------
__device__ float g_adjT[V_*LP1_*V_];     // [i][l][s] sigmoid(adj) transposed
__device__ float g_z [M_*V_*H_];
__device__ float g_z2[M_*V_*H_];
__device__ float g_q [M_*V_*H_];
__device__ float g_k [M_*V_*H_];
__device__ float g_v [M_*V_*H_];

// ---------------- stage 0: sigmoid + transpose of adjacency --------------
__global__ void prep_adj_kernel(const float* __restrict__ logits, float* __restrict__ adjT) {
    int idx = blockIdx.x * 256 + threadIdx.x;
    if (idx >= V_*V_*LP1_) return;
    // output layout adjT[(i*LP1+l)*V + s]
    int s = idx % V_;
    int r = idx / V_;
    int l = r % LP1_;
    int i = r / LP1_;
    float x = logits[(s*V_ + i)*LP1_ + l];
    adjT[idx] = 1.f / (1.f + __expf(-x));
}

// ---------------- stage 1: z[b,t,i,h] -------------------------------------
// one block per (b,t); 256 threads
__global__ __launch_bounds__(256)
void stage1_kernel(const float* __restrict__ x, const float* __restrict__ adjT,
                   const float* __restrict__ var_emb, const float* __restrict__ temp_emb,
                   float* __restrict__ z) {
    int bt = blockIdx.x;
    int b = bt >> 8;
    int t = bt & 255;
    __shared__ float xw[LP1_][V_];       // x window: xw[l][s] = x[b, t-l, s]
    __shared__ float Am[V_][V_ + 1];     // A[i][s]
    __shared__ float Bls[V_][LP1_ + 1];  // Bl[i][l]
    int tid = threadIdx.x;

    for (int p = tid; p < LP1_*V_; p += 256) {
        int l = p / V_, s = p % V_;
        int tt = t - l;
        xw[l][s] = (tt >= 0) ? x[((size_t)(b*S_ + tt))*V_ + s] : 0.f;
    }
    __syncthreads();

    // A[i][s] = sum_l xw[l][s] * adj[s,i,l]
    for (int p = tid; p < V_*V_; p += 256) {
        int i = p >> 6, s = p & 63;
        const float* ap = adjT + (size_t)i*LP1_*V_ + s;
        float a = 0.f;
        #pragma unroll
        for (int l = 0; l < LP1_; l++) a += xw[l][s] * ap[l*V_];
        Am[i][s] = a;
    }
    // Bl[i][l] = sum_s xw[l][s] * adj[s,i,l]
    for (int p = tid; p < V_*LP1_; p += 256) {
        int i = p / LP1_, l = p % LP1_;
        const float* ap = adjT + ((size_t)i*LP1_ + l)*V_;
        float a = 0.f;
        #pragma unroll 8
        for (int s = 0; s < V_; s++) a += xw[l][s] * ap[s];
        Bls[i][l] = a;
    }
    __syncthreads();

    // z[i][h] = A[i][:] @ var_emb + Bl[i][:] @ temp_emb
    int tx = tid & 15, ty = tid >> 4;       // thread tile: 4 rows(i) x 8 cols(h)
    float acc[4][8];
    #pragma unroll
    for (int r = 0; r < 4; r++)
        #pragma unroll
        for (int c = 0; c < 8; c++) acc[r][c] = 0.f;

    for (int s = 0; s < V_; s++) {
        float a0 = Am[ty*4+0][s], a1 = Am[ty*4+1][s], a2 = Am[ty*4+2][s], a3 = Am[ty*4+3][s];
        const float4* vp = (const float4*)(var_emb + (size_t)s*H_ + tx*8);
        float4 v0 = vp[0], v1 = vp[1];
        float bv[8] = {v0.x,v0.y,v0.z,v0.w,v1.x,v1.y,v1.z,v1.w};
        #pragma unroll
        for (int c = 0; c < 8; c++) {
            acc[0][c] += a0*bv[c]; acc[1][c] += a1*bv[c];
            acc[2][c] += a2*bv[c]; acc[3][c] += a3*bv[c];
        }
    }
    #pragma unroll
    for (int l = 0; l < LP1_; l++) {
        float a0 = Bls[ty*4+0][l], a1 = Bls[ty*4+1][l], a2 = Bls[ty*4+2][l], a3 = Bls[ty*4+3][l];
        const float4* vp = (const float4*)(temp_emb + (size_t)l*H_ + tx*8);
        float4 v0 = vp[0], v1 = vp[1];
        float bv[8] = {v0.x,v0.y,v0.z,v0.w,v1.x,v1.y,v1.z,v1.w};
        #pragma unroll
        for (int c = 0; c < 8; c++) {
            acc[0][c] += a0*bv[c]; acc[1][c] += a1*bv[c];
            acc[2][c] += a2*bv[c]; acc[3][c] += a3*bv[c];
        }
    }
    #pragma unroll
    for (int r = 0; r < 4; r++) {
        int i = ty*4 + r;
        float* zp = z + ((size_t)bt*V_ + i)*H_ + tx*8;
        *(float4*)(zp)   = make_float4(acc[r][0], acc[r][1], acc[r][2], acc[r][3]);
        *(float4*)(zp+4) = make_float4(acc[r][4], acc[r][5], acc[r][6], acc[r][7]);
    }
}

// ---------------- per-variable GEMM with fused epilogues ------------------
// A is (M, V, H) sliced at variable v (rows strided by V*H).
// W is per-variable (H,H) at stride w_vs, bias per-variable (H) at stride b_vs.
// MODE 0: out = acc + bias                       (QKV projections)
// MODE 1: out = GELU(LN(acc + bias) * g + b)     (mech layers)
// MODE 2: predictions = (acc + bias) . outW + outB   (O-proj + head, writes (M,V))
#define BM_ 64
#define BK_ 16
template <int MODE>
__global__ __launch_bounds__(256)
void vgemm_kernel(const float* __restrict__ A, const float* __restrict__ W,
                  const float* __restrict__ bias,
                  const float* __restrict__ lng, const float* __restrict__ lnb,
                  const float* __restrict__ oW,  const float* __restrict__ oB,
                  float* __restrict__ out, int w_vs, int b_vs) {
    int v  = blockIdx.y;
    int m0 = blockIdx.x * BM_;
    __shared__ float As[BK_][BM_ + 4];   // stride 68 (float4-aligned, conflict-spread)
    __shared__ float Bs[BK_][H_];
    __shared__ float red[2][BM_][17];

    int tid = threadIdx.x;
    int tx = tid & 15, ty = tid >> 4;   // tx -> N (8 cols each), ty -> M (4 rows each)
    const float* Wv = W + (size_t)v * w_vs;

    float acc[4][8];
    #pragma unroll
    for (int r = 0; r < 4; r++)
        #pragma unroll
        for (int c = 0; c < 8; c++) acc[r][c] = 0.f;

    for (int k0 = 0; k0 < H_; k0 += BK_) {
        {   // A tile: 64 rows x 16 k, transposed into As[k][row]
            int row = tid >> 2, c4 = (tid & 3) * 4;
            const float4 av = *(const float4*)(A + ((size_t)(m0+row)*V_ + v)*H_ + k0 + c4);
            As[c4+0][row] = av.x; As[c4+1][row] = av.y;
            As[c4+2][row] = av.z; As[c4+3][row] = av.w;
        }
        {   // B tile: 16 k x 128 n
            #pragma unroll
            for (int e = 0; e < 2; e++) {
                int idx = tid*2 + e;
                int kr = idx >> 5, c4 = (idx & 31) * 4;
                *(float4*)&Bs[kr][c4] = *(const float4*)(Wv + (size_t)(k0+kr)*H_ + c4);
            }
        }
        __syncthreads();
        #pragma unroll
        for (int kk = 0; kk < BK_; kk++) {
            float4 a4 = *(float4*)&As[kk][ty*4];
            float4 b0 = *(float4*)&Bs[kk][tx*8];
            float4 b1 = *(float4*)&Bs[kk][tx*8+4];
            float av[4] = {a4.x, a4.y, a4.z, a4.w};
            float bv[8] = {b0.x,b0.y,b0.z,b0.w,b1.x,b1.y,b1.z,b1.w};
            #pragma unroll
            for (int r = 0; r < 4; r++)
                #pragma unroll
                for (int c = 0; c < 8; c++) acc[r][c] += av[r]*bv[c];
        }
        __syncthreads();
    }

    // bias
    {
        const float* bp = bias + (size_t)v*b_vs + tx*8;
        float bb[8];
        #pragma unroll
        for (int c = 0; c < 8; c++) bb[c] = bp[c];
        #pragma unroll
        for (int r = 0; r < 4; r++)
            #pragma unroll
            for (int c = 0; c < 8; c++) acc[r][c] += bb[c];
    }

    if constexpr (MODE == 1) {
        #pragma unroll
        for (int r = 0; r < 4; r++) {
            float s = 0.f, q = 0.f;
            #pragma unroll
            for (int c = 0; c < 8; c++) { s += acc[r][c]; q += acc[r][c]*acc[r][c]; }
            red[0][ty*4+r][tx] = s;
            red[1][ty*4+r][tx] = q;
        }
        __syncthreads();
        float gg[8], lb[8];
        {
            const float* gp = lng + (size_t)v*b_vs + tx*8;
            const float* lp = lnb + (size_t)v*b_vs + tx*8;
            #pragma unroll
            for (int c = 0; c < 8; c++) { gg[c] = gp[c]; lb[c] = lp[c]; }
        }
        #pragma unroll
        for (int r = 0; r < 4; r++) {
            int row = ty*4 + r;
            float s = 0.f, q = 0.f;
            #pragma unroll
            for (int j = 0; j < 16; j++) { s += red[0][row][j]; q += red[1][row][j]; }
            float mean = s * (1.f/128.f);
            float var  = q * (1.f/128.f) - mean*mean;
            float rstd = rsqrtf(var + 1e-5f);
            float o_[8];
            #pragma unroll
            for (int c = 0; c < 8; c++) {
                float t2 = (acc[r][c] - mean) * rstd * gg[c] + lb[c];
                o_[c] = 0.5f * t2 * (1.f + erff(t2 * 0.7071067811865476f));
            }
            float* op = out + ((size_t)(m0+row)*V_ + v)*H_ + tx*8;
            *(float4*)(op)   = make_float4(o_[0], o_[1], o_[2], o_[3]);
            *(float4*)(op+4) = make_float4(o_[4], o_[5], o_[6], o_[7]);
        }
    } else if constexpr (MODE == 0) {
        #pragma unroll
        for (int r = 0; r < 4; r++) {
            float* op = out + ((size_t)(m0+ty*4+r)*V_ + v)*H_ + tx*8;
            *(float4*)(op)   = make_float4(acc[r][0], acc[r][1], acc[r][2], acc[r][3]);
            *(float4*)(op+4) = make_float4(acc[r][4], acc[r][5], acc[r][6], acc[r][7]);
        }
    } else {  // MODE == 2: output head fused
        float ow[8];
        {
            const float* wp = oW + (size_t)v*H_ + tx*8;
            #pragma unroll
            for (int c = 0; c < 8; c++) ow[c] = wp[c];
        }
        #pragma unroll
        for (int r = 0; r < 4; r++) {
            float p = 0.f;
            #pragma unroll
            for (int c = 0; c < 8; c++) p += acc[r][c]*ow[c];
            red[0][ty*4+r][tx] = p;
        }
        __syncthreads();
        if (tx == 0) {
            float ob = oB[v];
            #pragma unroll
            for (int r = 0; r < 4; r++) {
                int row = ty*4 + r;
                float s = 0.f;
                #pragma unroll
                for (int j = 0; j < 16; j++) s += red[0][row][j];
                out[(size_t)(m0+row)*V_ + v] = s + ob;
            }
        }
    }
}

// ---------------- attention: one block per (b, v, head) -------------------
__global__ __launch_bounds__(256)
void attn_kernel(const float* __restrict__ q, const float* __restrict__ k,
                 const float* __restrict__ vv, float* __restrict__ o) {
    int bid = blockIdx.x;            // b*V*NH + v*NH + n
    int n = bid & 7;
    int v = (bid >> 3) & 63;
    int b = bid >> 9;
    __shared__ float Ks[S_][DH_];
    __shared__ float Vs[S_][DH_];
    int t = threadIdx.x;             // query index (256 = S)

    size_t rowstride = (size_t)V_ * H_;
    size_t base = ((size_t)(b*S_)*V_ + v)*H_ + n*DH_;

    {   // stage K, V rows
        const float4* kp = (const float4*)(k  + base + (size_t)t*rowstride);
        const float4* vp = (const float4*)(vv + base + (size_t)t*rowstride);
        float4 k0 = kp[0], k1 = kp[1], k2 = kp[2], k3 = kp[3];
        float4 w0 = vp[0], w1 = vp[1], w2 = vp[2], w3 = vp[3];
        *(float4*)&Ks[t][0]  = k0; *(float4*)&Ks[t][4]  = k1;
        *(float4*)&Ks[t][8]  = k2; *(float4*)&Ks[t][12] = k3;
        *(float4*)&Vs[t][0]  = w0; *(float4*)&Vs[t][4]  = w1;
        *(float4*)&Vs[t][8]  = w2; *(float4*)&Vs[t][12] = w3;
    }
    float4 q0, q1, q2, q3;
    {
        const float4* qp = (const float4*)(q + base + (size_t)t*rowstride);
        q0 = qp[0]; q1 = qp[1]; q2 = qp[2]; q3 = qp[3];
    }
    __syncthreads();

    float m = -1e30f, ssum = 0.f;
    float av[16];
    #pragma unroll
    for (int d = 0; d < 16; d++) av[d] = 0.f;

    for (int j = 0; j < S_; j++) {
        float4 k0 = *(float4*)&Ks[j][0],  k1 = *(float4*)&Ks[j][4];
        float4 k2 = *(float4*)&Ks[j][8],  k3 = *(float4*)&Ks[j][12];
        float s = q0.x*k0.x + q0.y*k0.y + q0.z*k0.z + q0.w*k0.w
                + q1.x*k1.x + q1.y*k1.y + q1.z*k1.z + q1.w*k1.w
                + q2.x*k2.x + q2.y*k2.y + q2.z*k2.z + q2.w*k2.w
                + q3.x*k3.x + q3.y*k3.y + q3.z*k3.z + q3.w*k3.w;
        s *= 0.25f;   // 1/sqrt(DH)
        if (s > m) {
            float corr = __expf(m - s);
            ssum *= corr;
            #pragma unroll
            for (int d = 0; d < 16; d++) av[d] *= corr;
            m = s;
        }
        float e = __expf(s - m);
        ssum += e;
        float4 w0 = *(float4*)&Vs[j][0],  w1 = *(float4*)&Vs[j][4];
        float4 w2 = *(float4*)&Vs[j][8],  w3 = *(float4*)&Vs[j][12];
        av[0]  += e*w0.x; av[1]  += e*w0.y; av[2]  += e*w0.z; av[3]  += e*w0.w;
        av[4]  += e*w1.x; av[5]  += e*w1.y; av[6]  += e*w1.z; av[7]  += e*w1.w;
        av[8]  += e*w2.x; av[9]  += e*w2.y; av[10] += e*w2.z; av[11] += e*w2.w;
        av[12] += e*w3.x; av[13] += e*w3.y; av[14] += e*w3.z; av[15] += e*w3.w;
    }
    float inv = 1.f / ssum;
    float* op = o + base + (size_t)t*rowstride;
    *(float4*)(op)    = make_float4(av[0]*inv,  av[1]*inv,  av[2]*inv,  av[3]*inv);
    *(float4*)(op+4)  = make_float4(av[4]*inv,  av[5]*inv,  av[6]*inv,  av[7]*inv);
    *(float4*)(op+8)  = make_float4(av[8]*inv,  av[9]*inv,  av[10]*inv, av[11]*inv);
    *(float4*)(op+12) = make_float4(av[12]*inv, av[13]*inv, av[14]*inv, av[15]*inv);
}

// ---------------- launch ---------------------------------------------------
extern "C" void kernel_launch(void* const* d_in, const int* in_sizes, int n_in,
                              void* d_out, int out_size) {
    const float* x       = (const float*)d_in[0];
    const float* adjlog  = (const float*)d_in[1];
    const float* var_emb = (const float*)d_in[2];
    const float* temp_emb= (const float*)d_in[3];
    const float* mech_W  = (const float*)d_in[4];
    const float* mech_b  = (const float*)d_in[5];
    const float* ln_g    = (const float*)d_in[6];
    const float* ln_b    = (const float*)d_in[7];
    const float* Wq      = (const float*)d_in[8];
    const float* Wk      = (const float*)d_in[9];
    const float* Wv      = (const float*)d_in[10];
    const float* Wo      = (const float*)d_in[11];
    const float* bq      = (const float*)d_in[12];
    const float* bk      = (const float*)d_in[13];
    const float* bv      = (const float*)d_in[14];
    const float* bo      = (const float*)d_in[15];
    const float* out_W   = (const float*)d_in[16];
    const float* out_b   = (const float*)d_in[17];
    float* out = (float*)d_out;

    float *adjT, *z, *z2, *qb, *kb, *vb;
    cudaGetSymbolAddress((void**)&adjT, g_adjT);
    cudaGetSymbolAddress((void**)&z,    g_z);
    cudaGetSymbolAddress((void**)&z2,   g_z2);
    cudaGetSymbolAddress((void**)&qb,   g_q);
    cudaGetSymbolAddress((void**)&kb,   g_k);
    cudaGetSymbolAddress((void**)&vb,   g_v);

    prep_adj_kernel<<<(V_*V_*LP1_ + 255)/256, 256>>>(adjlog, adjT);
    stage1_kernel<<<M_, 256>>>(x, adjT, var_emb, temp_emb, z);

    dim3 gg(M_/BM_, V_);
    // mech layers (ping-pong z <-> z2)
    vgemm_kernel<1><<<gg, 256>>>(z,  mech_W + 0*H_*H_, mech_b + 0*H_, ln_g + 0*H_, ln_b + 0*H_,
                                 nullptr, nullptr, z2, NL_*H_*H_, NL_*H_);
    vgemm_kernel<1><<<gg, 256>>>(z2, mech_W + 1*H_*H_, mech_b + 1*H_, ln_g + 1*H_, ln_b + 1*H_,
                                 nullptr, nullptr, z,  NL_*H_*H_, NL_*H_);
    vgemm_kernel<1><<<gg, 256>>>(z,  mech_W + 2*H_*H_, mech_b + 2*H_, ln_g + 2*H_, ln_b + 2*H_,
                                 nullptr, nullptr, z2, NL_*H_*H_, NL_*H_);
    // QKV projections
    vgemm_kernel<0><<<gg, 256>>>(z2, Wq, bq, nullptr, nullptr, nullptr, nullptr, qb, H_*H_, H_);
    vgemm_kernel<0><<<gg, 256>>>(z2, Wk, bk, nullptr, nullptr, nullptr, nullptr, kb, H_*H_, H_);
    vgemm_kernel<0><<<gg, 256>>>(z2, Wv, bv, nullptr, nullptr, nullptr, nullptr, vb, H_*H_, H_);
    // attention -> z (reused as o buffer)
    attn_kernel<<<B_*V_*NH_, 256>>>(qb, kb, vb, z);
    // O-proj + output head fused -> predictions (B,S,V)
    vgemm_kernel<2><<<gg, 256>>>(z, Wo, bo, nullptr, nullptr, out_W, out_b, out, H_*H_, H_);
}

// round 3
// speedup vs baseline: 1.2714x; 1.2714x over previous
#include <cuda_runtime.h>
#include <math.h>

#define B_   4
#define S_   256
#define V_   64
#define LP1_ 11
#define H_   128
#define NH_  8
#define DH_  16
#define NL_  3
#define M_   (B_*S_)   // 1024

// ---------------- scratch (device globals; no allocation) ----------------
__device__ float g_adjT[V_*LP1_*V_];     // [i][l][s] sigmoid(adj) transposed
__device__ float g_z [M_*V_*H_];
__device__ float g_z2[M_*V_*H_];
__device__ float g_qkv[3*M_*V_*H_];      // packed q,k,v

// ---------------- stage 0: sigmoid + transpose of adjacency --------------
__global__ void prep_adj_kernel(const float* __restrict__ logits, float* __restrict__ adjT) {
    int idx = blockIdx.x * 256 + threadIdx.x;
    if (idx >= V_*V_*LP1_) return;
    int s = idx % V_;
    int r = idx / V_;
    int l = r % LP1_;
    int i = r / LP1_;
    float x = logits[(s*V_ + i)*LP1_ + l];
    adjT[idx] = 1.f / (1.f + __expf(-x));
}

// ---------------- stage 1: z[b,t,i,h] -------------------------------------
__global__ __launch_bounds__(256)
void stage1_kernel(const float* __restrict__ x, const float* __restrict__ adjT,
                   const float* __restrict__ var_emb, const float* __restrict__ temp_emb,
                   float* __restrict__ z) {
    int bt = blockIdx.x;
    int b = bt >> 8;
    int t = bt & 255;
    __shared__ float xw[LP1_][V_];
    __shared__ float Am[V_][V_ + 1];
    __shared__ float Bls[V_][LP1_ + 1];
    int tid = threadIdx.x;

    for (int p = tid; p < LP1_*V_; p += 256) {
        int l = p / V_, s = p % V_;
        int tt = t - l;
        xw[l][s] = (tt >= 0) ? x[((size_t)(b*S_ + tt))*V_ + s] : 0.f;
    }
    __syncthreads();

    for (int p = tid; p < V_*V_; p += 256) {
        int i = p >> 6, s = p & 63;
        const float* ap = adjT + (size_t)i*LP1_*V_ + s;
        float a = 0.f;
        #pragma unroll
        for (int l = 0; l < LP1_; l++) a += xw[l][s] * ap[l*V_];
        Am[i][s] = a;
    }
    for (int p = tid; p < V_*LP1_; p += 256) {
        int i = p / LP1_, l = p % LP1_;
        const float* ap = adjT + ((size_t)i*LP1_ + l)*V_;
        float a = 0.f;
        #pragma unroll 8
        for (int s = 0; s < V_; s++) a += xw[l][s] * ap[s];
        Bls[i][l] = a;
    }
    __syncthreads();

    int tx = tid & 15, ty = tid >> 4;
    float acc[4][8];
    #pragma unroll
    for (int r = 0; r < 4; r++)
        #pragma unroll
        for (int c = 0; c < 8; c++) acc[r][c] = 0.f;

    for (int s = 0; s < V_; s++) {
        float a0 = Am[ty*4+0][s], a1 = Am[ty*4+1][s], a2 = Am[ty*4+2][s], a3 = Am[ty*4+3][s];
        const float4* vp = (const float4*)(var_emb + (size_t)s*H_ + tx*8);
        float4 v0 = vp[0], v1 = vp[1];
        float bv[8] = {v0.x,v0.y,v0.z,v0.w,v1.x,v1.y,v1.z,v1.w};
        #pragma unroll
        for (int c = 0; c < 8; c++) {
            acc[0][c] += a0*bv[c]; acc[1][c] += a1*bv[c];
            acc[2][c] += a2*bv[c]; acc[3][c] += a3*bv[c];
        }
    }
    #pragma unroll
    for (int l = 0; l < LP1_; l++) {
        float a0 = Bls[ty*4+0][l], a1 = Bls[ty*4+1][l], a2 = Bls[ty*4+2][l], a3 = Bls[ty*4+3][l];
        const float4* vp = (const float4*)(temp_emb + (size_t)l*H_ + tx*8);
        float4 v0 = vp[0], v1 = vp[1];
        float bv[8] = {v0.x,v0.y,v0.z,v0.w,v1.x,v1.y,v1.z,v1.w};
        #pragma unroll
        for (int c = 0; c < 8; c++) {
            acc[0][c] += a0*bv[c]; acc[1][c] += a1*bv[c];
            acc[2][c] += a2*bv[c]; acc[3][c] += a3*bv[c];
        }
    }
    #pragma unroll
    for (int r = 0; r < 4; r++) {
        int i = ty*4 + r;
        float* zp = z + ((size_t)bt*V_ + i)*H_ + tx*8;
        *(float4*)(zp)   = make_float4(acc[r][0], acc[r][1], acc[r][2], acc[r][3]);
        *(float4*)(zp+4) = make_float4(acc[r][4], acc[r][5], acc[r][6], acc[r][7]);
    }
}

// ---------------- per-variable GEMM, 128x128 tile, 8x8 micro-tile ---------
// MODE 0: out = acc + bias        (QKV; blockIdx.z selects {Wq,Wk,Wv} via W2/W3 args)
// MODE 1: out = GELU(LN(acc+bias)*g + b)
// MODE 2: predictions = (acc+bias) . outW + outB
#define BM_ 128
#define BK_ 16
template <int MODE>
__global__ __launch_bounds__(256, 2)
void vgemm_kernel(const float* __restrict__ A,
                  const float* __restrict__ W0, const float* __restrict__ b0,
                  const float* __restrict__ W1, const float* __restrict__ b1,
                  const float* __restrict__ W2, const float* __restrict__ b2,
                  const float* __restrict__ oW, const float* __restrict__ oB,
                  float* __restrict__ out, int w_vs, int b_vs) {
    int v  = blockIdx.y;
    int m0 = blockIdx.x * BM_;
    __shared__ float As[BK_][BM_ + 4];   // stride 132 floats (16B-aligned rows)
    __shared__ float Bs[BK_][H_];
    __shared__ float red[2][BM_][17];

    int tid = threadIdx.x;
    int tx = tid & 15, ty = tid >> 4;   // tx -> cols {tx*4..+3, 64+tx*4..+3}; ty -> rows ty*8..+7

    const float* W = W0;
    const float* bias = b0;
    if (MODE == 0) {
        if (blockIdx.z == 1) { W = W1; bias = b1; }
        else if (blockIdx.z == 2) { W = W2; bias = b2; }
        out += (size_t)blockIdx.z * M_ * V_ * H_;
    }
    const float* Wv = W + (size_t)v * w_vs;

    float acc[8][8];
    #pragma unroll
    for (int r = 0; r < 8; r++)
        #pragma unroll
        for (int c = 0; c < 8; c++) acc[r][c] = 0.f;

    int arow = tid >> 1;
    int akc  = (tid & 1) * 8;
    const float* aptr = A + ((size_t)(m0 + arow)*V_ + v)*H_ + akc;

    for (int k0 = 0; k0 < H_; k0 += BK_) {
        {   // A tile: 128 rows x 16 k, transposed into As[k][row]
            float4 a0 = *(const float4*)(aptr + k0);
            float4 a1 = *(const float4*)(aptr + k0 + 4);
            As[akc+0][arow] = a0.x; As[akc+1][arow] = a0.y;
            As[akc+2][arow] = a0.z; As[akc+3][arow] = a0.w;
            As[akc+4][arow] = a1.x; As[akc+5][arow] = a1.y;
            As[akc+6][arow] = a1.z; As[akc+7][arow] = a1.w;
        }
        {   // B tile: 16 k x 128 n (2 float4 per thread)
            #pragma unroll
            for (int e = 0; e < 2; e++) {
                int idx = tid*2 + e;
                int kr = idx >> 5, c4 = (idx & 31) * 4;
                *(float4*)&Bs[kr][c4] = *(const float4*)(Wv + (size_t)(k0+kr)*H_ + c4);
            }
        }
        __syncthreads();
        #pragma unroll
        for (int kk = 0; kk < BK_; kk++) {
            float4 aA = *(float4*)&As[kk][ty*8];
            float4 aB = *(float4*)&As[kk][ty*8+4];
            float4 bA = *(float4*)&Bs[kk][tx*4];
            float4 bB = *(float4*)&Bs[kk][64 + tx*4];
            float av[8] = {aA.x,aA.y,aA.z,aA.w,aB.x,aB.y,aB.z,aB.w};
            float bv[8] = {bA.x,bA.y,bA.z,bA.w,bB.x,bB.y,bB.z,bB.w};
            #pragma unroll
            for (int r = 0; r < 8; r++)
                #pragma unroll
                for (int c = 0; c < 8; c++) acc[r][c] += av[r]*bv[c];
        }
        __syncthreads();
    }

    // bias (cols tx*4..+3 and 64+tx*4..+3)
    {
        const float* bp = bias + (size_t)v*b_vs;
        float4 bb0 = *(const float4*)(bp + tx*4);
        float4 bb1 = *(const float4*)(bp + 64 + tx*4);
        float bb[8] = {bb0.x,bb0.y,bb0.z,bb0.w,bb1.x,bb1.y,bb1.z,bb1.w};
        #pragma unroll
        for (int r = 0; r < 8; r++)
            #pragma unroll
            for (int c = 0; c < 8; c++) acc[r][c] += bb[c];
    }

    if constexpr (MODE == 1) {
        #pragma unroll
        for (int r = 0; r < 8; r++) {
            float s = 0.f, q = 0.f;
            #pragma unroll
            for (int c = 0; c < 8; c++) { s += acc[r][c]; q += acc[r][c]*acc[r][c]; }
            red[0][ty*8+r][tx] = s;
            red[1][ty*8+r][tx] = q;
        }
        __syncthreads();
        float gg[8], lb[8];
        {
            const float* gp = W1 + (size_t)v*b_vs;   // ln gamma
            const float* lp = b1 + (size_t)v*b_vs;   // ln beta
            float4 g0 = *(const float4*)(gp + tx*4), g1 = *(const float4*)(gp + 64 + tx*4);
            float4 l0 = *(const float4*)(lp + tx*4), l1 = *(const float4*)(lp + 64 + tx*4);
            gg[0]=g0.x;gg[1]=g0.y;gg[2]=g0.z;gg[3]=g0.w;gg[4]=g1.x;gg[5]=g1.y;gg[6]=g1.z;gg[7]=g1.w;
            lb[0]=l0.x;lb[1]=l0.y;lb[2]=l0.z;lb[3]=l0.w;lb[4]=l1.x;lb[5]=l1.y;lb[6]=l1.z;lb[7]=l1.w;
        }
        #pragma unroll
        for (int r = 0; r < 8; r++) {
            int row = ty*8 + r;
            float s = 0.f, q = 0.f;
            #pragma unroll
            for (int j = 0; j < 16; j++) { s += red[0][row][j]; q += red[1][row][j]; }
            float mean = s * (1.f/128.f);
            float var  = q * (1.f/128.f) - mean*mean;
            float rstd = rsqrtf(var + 1e-5f);
            float o_[8];
            #pragma unroll
            for (int c = 0; c < 8; c++) {
                float t2 = (acc[r][c] - mean) * rstd * gg[c] + lb[c];
                o_[c] = 0.5f * t2 * (1.f + erff(t2 * 0.7071067811865476f));
            }
            float* op = out + ((size_t)(m0+row)*V_ + v)*H_;
            *(float4*)(op + tx*4)      = make_float4(o_[0], o_[1], o_[2], o_[3]);
            *(float4*)(op + 64 + tx*4) = make_float4(o_[4], o_[5], o_[6], o_[7]);
        }
    } else if constexpr (MODE == 0) {
        #pragma unroll
        for (int r = 0; r < 8; r++) {
            float* op = out + ((size_t)(m0+ty*8+r)*V_ + v)*H_;
            *(float4*)(op + tx*4)      = make_float4(acc[r][0], acc[r][1], acc[r][2], acc[r][3]);
            *(float4*)(op + 64 + tx*4) = make_float4(acc[r][4], acc[r][5], acc[r][6], acc[r][7]);
        }
    } else {  // MODE == 2: O-proj + output head fused
        float ow[8];
        {
            const float* wp = oW + (size_t)v*H_;
            float4 w0 = *(const float4*)(wp + tx*4), w1 = *(const float4*)(wp + 64 + tx*4);
            ow[0]=w0.x;ow[1]=w0.y;ow[2]=w0.z;ow[3]=w0.w;ow[4]=w1.x;ow[5]=w1.y;ow[6]=w1.z;ow[7]=w1.w;
        }
        #pragma unroll
        for (int r = 0; r < 8; r++) {
            float p = 0.f;
            #pragma unroll
            for (int c = 0; c < 8; c++) p += acc[r][c]*ow[c];
            red[0][ty*8+r][tx] = p;
        }
        __syncthreads();
        if (tx == 0) {
            float ob = oB[v];
            #pragma unroll
            for (int r = 0; r < 8; r++) {
                int row = ty*8 + r;
                float s = 0.f;
                #pragma unroll
                for (int j = 0; j < 16; j++) s += red[0][row][j];
                out[(size_t)(m0+row)*V_ + v] = s + ob;
            }
        }
    }
}

// ---------------- attention: one block per (b, v, head) -------------------
__global__ __launch_bounds__(256)
void attn_kernel(const float* __restrict__ qkv, float* __restrict__ o) {
    int bid = blockIdx.x;            // b*V*NH + v*NH + n
    int n = bid & 7;
    int v = (bid >> 3) & 63;
    int b = bid >> 9;
    __shared__ float Ks[S_][DH_];
    __shared__ float Vs[S_][DH_];
    int t = threadIdx.x;

    const float* q  = qkv;
    const float* k  = qkv + (size_t)M_*V_*H_;
    const float* vv = qkv + (size_t)2*M_*V_*H_;

    size_t rowstride = (size_t)V_ * H_;
    size_t base = ((size_t)(b*S_)*V_ + v)*H_ + n*DH_;

    {
        const float4* kp = (const float4*)(k  + base + (size_t)t*rowstride);
        const float4* vp = (const float4*)(vv + base + (size_t)t*rowstride);
        float4 k0 = kp[0], k1 = kp[1], k2 = kp[2], k3 = kp[3];
        float4 w0 = vp[0], w1 = vp[1], w2 = vp[2], w3 = vp[3];
        *(float4*)&Ks[t][0]  = k0; *(float4*)&Ks[t][4]  = k1;
        *(float4*)&Ks[t][8]  = k2; *(float4*)&Ks[t][12] = k3;
        *(float4*)&Vs[t][0]  = w0; *(float4*)&Vs[t][4]  = w1;
        *(float4*)&Vs[t][8]  = w2; *(float4*)&Vs[t][12] = w3;
    }
    float4 q0, q1, q2, q3;
    {
        const float4* qp = (const float4*)(q + base + (size_t)t*rowstride);
        q0 = qp[0]; q1 = qp[1]; q2 = qp[2]; q3 = qp[3];
    }
    __syncthreads();

    float m = -1e30f, ssum = 0.f;
    float av[16];
    #pragma unroll
    for (int d = 0; d < 16; d++) av[d] = 0.f;

    for (int j = 0; j < S_; j++) {
        float4 k0 = *(float4*)&Ks[j][0],  k1 = *(float4*)&Ks[j][4];
        float4 k2 = *(float4*)&Ks[j][8],  k3 = *(float4*)&Ks[j][12];
        float s = q0.x*k0.x + q0.y*k0.y + q0.z*k0.z + q0.w*k0.w
                + q1.x*k1.x + q1.y*k1.y + q1.z*k1.z + q1.w*k1.w
                + q2.x*k2.x + q2.y*k2.y + q2.z*k2.z + q2.w*k2.w
                + q3.x*k3.x + q3.y*k3.y + q3.z*k3.z + q3.w*k3.w;
        s *= 0.25f;
        if (s > m) {
            float corr = __expf(m - s);
            ssum *= corr;
            #pragma unroll
            for (int d = 0; d < 16; d++) av[d] *= corr;
            m = s;
        }
        float e = __expf(s - m);
        ssum += e;
        float4 w0 = *(float4*)&Vs[j][0],  w1 = *(float4*)&Vs[j][4];
        float4 w2 = *(float4*)&Vs[j][8],  w3 = *(float4*)&Vs[j][12];
        av[0]  += e*w0.x; av[1]  += e*w0.y; av[2]  += e*w0.z; av[3]  += e*w0.w;
        av[4]  += e*w1.x; av[5]  += e*w1.y; av[6]  += e*w1.z; av[7]  += e*w1.w;
        av[8]  += e*w2.x; av[9]  += e*w2.y; av[10] += e*w2.z; av[11] += e*w2.w;
        av[12] += e*w3.x; av[13] += e*w3.y; av[14] += e*w3.z; av[15] += e*w3.w;
    }
    float inv = 1.f / ssum;
    float* op = o + base + (size_t)t*rowstride;
    *(float4*)(op)    = make_float4(av[0]*inv,  av[1]*inv,  av[2]*inv,  av[3]*inv);
    *(float4*)(op+4)  = make_float4(av[4]*inv,  av[5]*inv,  av[6]*inv,  av[7]*inv);
    *(float4*)(op+8)  = make_float4(av[8]*inv,  av[9]*inv,  av[10]*inv, av[11]*inv);
    *(float4*)(op+12) = make_float4(av[12]*inv, av[13]*inv, av[14]*inv, av[15]*inv);
}

// ---------------- launch ---------------------------------------------------
extern "C" void kernel_launch(void* const* d_in, const int* in_sizes, int n_in,
                              void* d_out, int out_size) {
    const float* x       = (const float*)d_in[0];
    const float* adjlog  = (const float*)d_in[1];
    const float* var_emb = (const float*)d_in[2];
    const float* temp_emb= (const float*)d_in[3];
    const float* mech_W  = (const float*)d_in[4];
    const float* mech_b  = (const float*)d_in[5];
    const float* ln_g    = (const float*)d_in[6];
    const float* ln_b    = (const float*)d_in[7];
    const float* Wq      = (const float*)d_in[8];
    const float* Wk      = (const float*)d_in[9];
    const float* Wv      = (const float*)d_in[10];
    const float* Wo      = (const float*)d_in[11];
    const float* bq      = (const float*)d_in[12];
    const float* bk      = (const float*)d_in[13];
    const float* bv      = (const float*)d_in[14];
    const float* bo      = (const float*)d_in[15];
    const float* out_W   = (const float*)d_in[16];
    const float* out_b   = (const float*)d_in[17];
    float* out = (float*)d_out;

    float *adjT, *z, *z2, *qkv;
    cudaGetSymbolAddress((void**)&adjT, g_adjT);
    cudaGetSymbolAddress((void**)&z,    g_z);
    cudaGetSymbolAddress((void**)&z2,   g_z2);
    cudaGetSymbolAddress((void**)&qkv,  g_qkv);

    prep_adj_kernel<<<(V_*V_*LP1_ + 255)/256, 256>>>(adjlog, adjT);
    stage1_kernel<<<M_, 256>>>(x, adjT, var_emb, temp_emb, z);

    dim3 gg(M_/BM_, V_);
    // mech layers: W0=W, b0=bias, W1=ln_g slice, b1=ln_b slice
    vgemm_kernel<1><<<gg, 256>>>(z,  mech_W + 0*H_*H_, mech_b + 0*H_, ln_g + 0*H_, ln_b + 0*H_,
                                 nullptr, nullptr, nullptr, nullptr, z2, NL_*H_*H_, NL_*H_);
    vgemm_kernel<1><<<gg, 256>>>(z2, mech_W + 1*H_*H_, mech_b + 1*H_, ln_g + 1*H_, ln_b + 1*H_,
                                 nullptr, nullptr, nullptr, nullptr, z,  NL_*H_*H_, NL_*H_);
    vgemm_kernel<1><<<gg, 256>>>(z,  mech_W + 2*H_*H_, mech_b + 2*H_, ln_g + 2*H_, ln_b + 2*H_,
                                 nullptr, nullptr, nullptr, nullptr, z2, NL_*H_*H_, NL_*H_);
    // fused QKV: grid.z selects weight/bias/output slice
    dim3 gq(M_/BM_, V_, 3);
    vgemm_kernel<0><<<gq, 256>>>(z2, Wq, bq, Wk, bk, Wv, bv,
                                 nullptr, nullptr, qkv, H_*H_, H_);
    // attention -> z (reused as o buffer)
    attn_kernel<<<B_*V_*NH_, 256>>>(qkv, z);
    // O-proj + output head fused -> predictions (B,S,V)
    vgemm_kernel<2><<<gg, 256>>>(z, Wo, bo, nullptr, nullptr, nullptr, nullptr,
                                 out_W, out_b, out, H_*H_, H_);
}

// round 5
// speedup vs baseline: 1.2958x; 1.0192x over previous
#include <cuda_runtime.h>
#include <cuda_bf16.h>
#include <mma.h>
#include <math.h>
#include <stdint.h>

using namespace nvcuda;

#define B_   4
#define S_   256
#define V_   64
#define LP1_ 11
#define H_   128
#define NH_  8
#define DH_  16
#define NL_  3
#define M_   (B_*S_)   // 1024

// ---------------- scratch (device globals; no allocation) ----------------
__device__ float g_adjT[V_*LP1_*V_];
__device__ float g_z [M_*V_*H_];
__device__ float g_z2[M_*V_*H_];
__device__ float g_qkv[3*M_*V_*H_];

// ---------------- stage 0: sigmoid + transpose of adjacency --------------
__global__ void prep_adj_kernel(const float* __restrict__ logits, float* __restrict__ adjT) {
    int idx = blockIdx.x * 256 + threadIdx.x;
    if (idx >= V_*V_*LP1_) return;
    int s = idx % V_;
    int r = idx / V_;
    int l = r % LP1_;
    int i = r / LP1_;
    float x = logits[(s*V_ + i)*LP1_ + l];
    adjT[idx] = 1.f / (1.f + __expf(-x));
}

// ---------------- stage 1: z[b,t,i,h] -------------------------------------
__global__ __launch_bounds__(256)
void stage1_kernel(const float* __restrict__ x, const float* __restrict__ adjT,
                   const float* __restrict__ var_emb, const float* __restrict__ temp_emb,
                   float* __restrict__ z) {
    int bt = blockIdx.x;
    int b = bt >> 8;
    int t = bt & 255;
    __shared__ float xw[LP1_][V_];
    __shared__ float Am[V_][V_ + 1];
    __shared__ float Bls[V_][LP1_ + 1];
    int tid = threadIdx.x;

    for (int p = tid; p < LP1_*V_; p += 256) {
        int l = p / V_, s = p % V_;
        int tt = t - l;
        xw[l][s] = (tt >= 0) ? x[((size_t)(b*S_ + tt))*V_ + s] : 0.f;
    }
    __syncthreads();

    for (int p = tid; p < V_*V_; p += 256) {
        int i = p >> 6, s = p & 63;
        const float* ap = adjT + (size_t)i*LP1_*V_ + s;
        float a = 0.f;
        #pragma unroll
        for (int l = 0; l < LP1_; l++) a += xw[l][s] * ap[l*V_];
        Am[i][s] = a;
    }
    for (int p = tid; p < V_*LP1_; p += 256) {
        int i = p / LP1_, l = p % LP1_;
        const float* ap = adjT + ((size_t)i*LP1_ + l)*V_;
        float a = 0.f;
        #pragma unroll 8
        for (int s = 0; s < V_; s++) a += xw[l][s] * ap[s];
        Bls[i][l] = a;
    }
    __syncthreads();

    int tx = tid & 15, ty = tid >> 4;
    float acc[4][8];
    #pragma unroll
    for (int r = 0; r < 4; r++)
        #pragma unroll
        for (int c = 0; c < 8; c++) acc[r][c] = 0.f;

    for (int s = 0; s < V_; s++) {
        float a0 = Am[ty*4+0][s], a1 = Am[ty*4+1][s], a2 = Am[ty*4+2][s], a3 = Am[ty*4+3][s];
        const float4* vp = (const float4*)(var_emb + (size_t)s*H_ + tx*8);
        float4 v0 = vp[0], v1 = vp[1];
        float bv[8] = {v0.x,v0.y,v0.z,v0.w,v1.x,v1.y,v1.z,v1.w};
        #pragma unroll
        for (int c = 0; c < 8; c++) {
            acc[0][c] += a0*bv[c]; acc[1][c] += a1*bv[c];
            acc[2][c] += a2*bv[c]; acc[3][c] += a3*bv[c];
        }
    }
    #pragma unroll
    for (int l = 0; l < LP1_; l++) {
        float a0 = Bls[ty*4+0][l], a1 = Bls[ty*4+1][l], a2 = Bls[ty*4+2][l], a3 = Bls[ty*4+3][l];
        const float4* vp = (const float4*)(temp_emb + (size_t)l*H_ + tx*8);
        float4 v0 = vp[0], v1 = vp[1];
        float bv[8] = {v0.x,v0.y,v0.z,v0.w,v1.x,v1.y,v1.z,v1.w};
        #pragma unroll
        for (int c = 0; c < 8; c++) {
            acc[0][c] += a0*bv[c]; acc[1][c] += a1*bv[c];
            acc[2][c] += a2*bv[c]; acc[3][c] += a3*bv[c];
        }
    }
    #pragma unroll
    for (int r = 0; r < 4; r++) {
        int i = ty*4 + r;
        float* zp = z + ((size_t)bt*V_ + i)*H_ + tx*8;
        *(float4*)(zp)   = make_float4(acc[r][0], acc[r][1], acc[r][2], acc[r][3]);
        *(float4*)(zp+4) = make_float4(acc[r][4], acc[r][5], acc[r][6], acc[r][7]);
    }
}

// ============= wmma bf16-split per-variable GEMM (fp32-accurate) ===========
// smem layout (bytes, dynamic):
#define OFF_P0   0        // bias (512B)
#define OFF_P1   512      // ln gamma / head weight
#define OFF_P2   1024     // ln beta
#define OFF_T    2048     // tiles
#define LDT      136      // bf16 elems per tile row (padded)
#define TILE_B   (128*LDT*2)            // 34816 B per tile
#define OFF_AHI  (OFF_T)
#define OFF_ALO  (OFF_T + TILE_B)
#define OFF_BHI  (OFF_T + 2*TILE_B)
#define OFF_BLO  (OFF_T + 3*TILE_B)
#define GSM_TOTAL (OFF_T + 4*TILE_B)    // 141312 B
#define OFF_C    OFF_T                  // fp32 C overlaps tiles post-sync
#define LDC      132                    // floats per C row

__device__ __forceinline__ uint32_t pack_hi(float a, float b) {
    __nv_bfloat16 ha = __float2bfloat16(a), hb = __float2bfloat16(b);
    return ((uint32_t)__bfloat16_as_ushort(hb) << 16) | __bfloat16_as_ushort(ha);
}
__device__ __forceinline__ uint32_t pack_lo(float a, float b) {
    __nv_bfloat16 ha = __float2bfloat16(a), hb = __float2bfloat16(b);
    float ra = a - __bfloat162float(ha), rb = b - __bfloat162float(hb);
    __nv_bfloat16 la = __float2bfloat16(ra), lb = __float2bfloat16(rb);
    return ((uint32_t)__bfloat16_as_ushort(lb) << 16) | __bfloat16_as_ushort(la);
}

// fill one 128x128 tile (hi + lo) into smem bf16 rows of LDT
__device__ __forceinline__ void fill_split(char* smem, int hi_off, int lo_off,
                                           const float* __restrict__ src,
                                           size_t row_stride, int tid) {
    #pragma unroll
    for (int i = 0; i < 16; i++) {
        int f = tid + 256*i;
        int row = f >> 5, c4 = f & 31;        // 32 float4 per row
        float4 vv = *(const float4*)(src + (size_t)row*row_stride + c4*4);
        uint2 hv, lv;
        hv.x = pack_hi(vv.x, vv.y); hv.y = pack_hi(vv.z, vv.w);
        lv.x = pack_lo(vv.x, vv.y); lv.y = pack_lo(vv.z, vv.w);
        uint32_t boff = (uint32_t)row*(LDT*2) + (uint32_t)c4*8;
        *(uint2*)(smem + hi_off + boff) = hv;
        *(uint2*)(smem + lo_off + boff) = lv;
    }
}

// MODE 0: out = D + bias (QKV via blockIdx.z)
// MODE 1: out = GELU(LN(D + bias)*g + b)
// MODE 2: out[m,v] = (D + bias) . oW + oB
template <int MODE>
__global__ __launch_bounds__(256, 1)
void vgemm_wmma(const float* __restrict__ A, const float* __restrict__ W,
                const float* __restrict__ b0, const float* __restrict__ W1,
                const float* __restrict__ b1, const float* __restrict__ W2,
                const float* __restrict__ b2,
                const float* __restrict__ lng, const float* __restrict__ lnb,
                const float* __restrict__ oW, const float* __restrict__ oB,
                float* __restrict__ out, int w_vs, int b_vs) {
    extern __shared__ char smem[];
    int tid = threadIdx.x;
    int v = blockIdx.y, m0 = blockIdx.x * 128;

    const float* bias = b0;
    if (MODE == 0) {
        int zi = blockIdx.z;
        if (zi == 1) { W = W1; bias = b1; }
        else if (zi == 2) { W = W2; bias = b2; }
        out += (size_t)zi * M_ * V_ * H_;
    }

    float* sBias = (float*)(smem + OFF_P0);
    float* sG    = (float*)(smem + OFF_P1);
    float* sBeta = (float*)(smem + OFF_P2);
    if (tid < 128) {
        sBias[tid] = bias[(size_t)v*b_vs + tid];
        if (MODE == 1) {
            sG[tid]    = lng[(size_t)v*b_vs + tid];
            sBeta[tid] = lnb[(size_t)v*b_vs + tid];
        } else if (MODE == 2) {
            sG[tid] = oW[(size_t)v*H_ + tid];
        }
    }

    // A rows (activations, strided), B rows (weights, k-major: W[k][n])
    fill_split(smem, OFF_AHI, OFF_ALO, A + ((size_t)m0*V_ + v)*H_, (size_t)V_*H_, tid);
    fill_split(smem, OFF_BHI, OFF_BLO, W + (size_t)v*w_vs, (size_t)H_, tid);
    __syncthreads();

    int w = tid >> 5;
    int wm = w & 3;        // 4 warps over M (32 rows each)
    int wn = w >> 2;       // 2 warps over N (64 cols each)

    wmma::fragment<wmma::accumulator, 16, 16, 16, float> acc[2][4];
    #pragma unroll
    for (int mi = 0; mi < 2; mi++)
        #pragma unroll
        for (int ni = 0; ni < 4; ni++) wmma::fill_fragment(acc[mi][ni], 0.f);

    const __nv_bfloat16* aHi = (const __nv_bfloat16*)(smem + OFF_AHI);
    const __nv_bfloat16* aLo = (const __nv_bfloat16*)(smem + OFF_ALO);
    const __nv_bfloat16* bHi = (const __nv_bfloat16*)(smem + OFF_BHI);
    const __nv_bfloat16* bLo = (const __nv_bfloat16*)(smem + OFF_BLO);

    #pragma unroll
    for (int p = 0; p < 3; p++) {
        const __nv_bfloat16* aS = (p == 2) ? aLo : aHi;
        const __nv_bfloat16* bS = (p == 1) ? bLo : bHi;
        #pragma unroll
        for (int k0 = 0; k0 < 8; k0++) {
            int k = k0 * 16;
            wmma::fragment<wmma::matrix_a, 16, 16, 16, __nv_bfloat16, wmma::row_major> af[2];
            wmma::fragment<wmma::matrix_b, 16, 16, 16, __nv_bfloat16, wmma::row_major> bf[4];
            #pragma unroll
            for (int mi = 0; mi < 2; mi++)
                wmma::load_matrix_sync(af[mi], aS + (size_t)(wm*32 + mi*16)*LDT + k, LDT);
            #pragma unroll
            for (int ni = 0; ni < 4; ni++)
                wmma::load_matrix_sync(bf[ni], bS + (size_t)k*LDT + wn*64 + ni*16, LDT);
            #pragma unroll
            for (int mi = 0; mi < 2; mi++)
                #pragma unroll
                for (int ni = 0; ni < 4; ni++)
                    wmma::mma_sync(acc[mi][ni], af[mi], bf[ni], acc[mi][ni]);
        }
    }
    __syncthreads();   // done reading tiles; reuse region as fp32 C

    float* Cs = (float*)(smem + OFF_C);
    #pragma unroll
    for (int mi = 0; mi < 2; mi++)
        #pragma unroll
        for (int ni = 0; ni < 4; ni++)
            wmma::store_matrix_sync(Cs + (size_t)(wm*32 + mi*16)*LDC + wn*64 + ni*16,
                                    acc[mi][ni], LDC, wmma::mem_row_major);
    __syncthreads();

    // ---- row-wise epilogue: thread t < 128 owns output row t ----
    if (tid < 128) {
        int row = m0 + tid;
        float y[128];
        #pragma unroll
        for (int c = 0; c < 128; c += 4) {
            float4 c4 = *(float4*)(Cs + (size_t)tid*LDC + c);
            y[c]   = c4.x + sBias[c];
            y[c+1] = c4.y + sBias[c+1];
            y[c+2] = c4.z + sBias[c+2];
            y[c+3] = c4.w + sBias[c+3];
        }
        if constexpr (MODE == 1) {
            float s = 0.f, q = 0.f;
            #pragma unroll
            for (int c = 0; c < 128; c++) { s += y[c]; q += y[c]*y[c]; }
            float mean = s * (1.f/128.f);
            float var  = q * (1.f/128.f) - mean*mean;
            float rstd = rsqrtf(var + 1e-5f);
            float* orow = out + ((size_t)row*V_ + v)*H_;
            #pragma unroll
            for (int c = 0; c < 128; c += 4) {
                float o4[4];
                #pragma unroll
                for (int j = 0; j < 4; j++) {
                    float t2 = (y[c+j] - mean) * rstd * sG[c+j] + sBeta[c+j];
                    o4[j] = 0.5f * t2 * (1.f + erff(t2 * 0.7071067811865476f));
                }
                *(float4*)(orow + c) = make_float4(o4[0], o4[1], o4[2], o4[3]);
            }
        } else if constexpr (MODE == 0) {
            float* orow = out + ((size_t)row*V_ + v)*H_;
            #pragma unroll
            for (int c = 0; c < 128; c += 4)
                *(float4*)(orow + c) = make_float4(y[c], y[c+1], y[c+2], y[c+3]);
        } else {
            float p = 0.f;
            #pragma unroll
            for (int c = 0; c < 128; c++) p += y[c] * sG[c];
            out[(size_t)row*V_ + v] = p + oB[v];
        }
    }
}

// ---------------- attention: one block per (b, v, head) -------------------
__global__ __launch_bounds__(256)
void attn_kernel(const float* __restrict__ qkv, float* __restrict__ o) {
    int bid = blockIdx.x;
    int n = bid & 7;
    int v = (bid >> 3) & 63;
    int b = bid >> 9;
    __shared__ float Ks[S_][DH_];
    __shared__ float Vs[S_][DH_];
    int t = threadIdx.x;

    const float* q  = qkv;
    const float* k  = qkv + (size_t)M_*V_*H_;
    const float* vv = qkv + (size_t)2*M_*V_*H_;

    size_t rowstride = (size_t)V_ * H_;
    size_t base = ((size_t)(b*S_)*V_ + v)*H_ + n*DH_;

    {
        const float4* kp = (const float4*)(k  + base + (size_t)t*rowstride);
        const float4* vp = (const float4*)(vv + base + (size_t)t*rowstride);
        float4 k0 = kp[0], k1 = kp[1], k2 = kp[2], k3 = kp[3];
        float4 w0 = vp[0], w1 = vp[1], w2 = vp[2], w3 = vp[3];
        *(float4*)&Ks[t][0]  = k0; *(float4*)&Ks[t][4]  = k1;
        *(float4*)&Ks[t][8]  = k2; *(float4*)&Ks[t][12] = k3;
        *(float4*)&Vs[t][0]  = w0; *(float4*)&Vs[t][4]  = w1;
        *(float4*)&Vs[t][8]  = w2; *(float4*)&Vs[t][12] = w3;
    }
    float4 q0, q1, q2, q3;
    {
        const float4* qp = (const float4*)(q + base + (size_t)t*rowstride);
        q0 = qp[0]; q1 = qp[1]; q2 = qp[2]; q3 = qp[3];
    }
    __syncthreads();

    float m = -1e30f, ssum = 0.f;
    float av[16];
    #pragma unroll
    for (int d = 0; d < 16; d++) av[d] = 0.f;

    for (int j = 0; j < S_; j++) {
        float4 k0 = *(float4*)&Ks[j][0],  k1 = *(float4*)&Ks[j][4];
        float4 k2 = *(float4*)&Ks[j][8],  k3 = *(float4*)&Ks[j][12];
        float s = q0.x*k0.x + q0.y*k0.y + q0.z*k0.z + q0.w*k0.w
                + q1.x*k1.x + q1.y*k1.y + q1.z*k1.z + q1.w*k1.w
                + q2.x*k2.x + q2.y*k2.y + q2.z*k2.z + q2.w*k2.w
                + q3.x*k3.x + q3.y*k3.y + q3.z*k3.z + q3.w*k3.w;
        s *= 0.25f;
        if (s > m) {
            float corr = __expf(m - s);
            ssum *= corr;
            #pragma unroll
            for (int d = 0; d < 16; d++) av[d] *= corr;
            m = s;
        }
        float e = __expf(s - m);
        ssum += e;
        float4 w0 = *(float4*)&Vs[j][0],  w1 = *(float4*)&Vs[j][4];
        float4 w2 = *(float4*)&Vs[j][8],  w3 = *(float4*)&Vs[j][12];
        av[0]  += e*w0.x; av[1]  += e*w0.y; av[2]  += e*w0.z; av[3]  += e*w0.w;
        av[4]  += e*w1.x; av[5]  += e*w1.y; av[6]  += e*w1.z; av[7]  += e*w1.w;
        av[8]  += e*w2.x; av[9]  += e*w2.y; av[10] += e*w2.z; av[11] += e*w2.w;
        av[12] += e*w3.x; av[13] += e*w3.y; av[14] += e*w3.z; av[15] += e*w3.w;
    }
    float inv = 1.f / ssum;
    float* op = o + base + (size_t)t*rowstride;
    *(float4*)(op)    = make_float4(av[0]*inv,  av[1]*inv,  av[2]*inv,  av[3]*inv);
    *(float4*)(op+4)  = make_float4(av[4]*inv,  av[5]*inv,  av[6]*inv,  av[7]*inv);
    *(float4*)(op+8)  = make_float4(av[8]*inv,  av[9]*inv,  av[10]*inv, av[11]*inv);
    *(float4*)(op+12) = make_float4(av[12]*inv, av[13]*inv, av[14]*inv, av[15]*inv);
}

// ---------------- launch ---------------------------------------------------
extern "C" void kernel_launch(void* const* d_in, const int* in_sizes, int n_in,
                              void* d_out, int out_size) {
    const float* x       = (const float*)d_in[0];
    const float* adjlog  = (const float*)d_in[1];
    const float* var_emb = (const float*)d_in[2];
    const float* temp_emb= (const float*)d_in[3];
    const float* mech_W  = (const float*)d_in[4];
    const float* mech_b  = (const float*)d_in[5];
    const float* ln_g    = (const float*)d_in[6];
    const float* ln_b    = (const float*)d_in[7];
    const float* Wq      = (const float*)d_in[8];
    const float* Wk      = (const float*)d_in[9];
    const float* Wv      = (const float*)d_in[10];
    const float* Wo      = (const float*)d_in[11];
    const float* bq      = (const float*)d_in[12];
    const float* bk      = (const float*)d_in[13];
    const float* bv      = (const float*)d_in[14];
    const float* bo      = (const float*)d_in[15];
    const float* out_W   = (const float*)d_in[16];
    const float* out_b   = (const float*)d_in[17];
    float* out = (float*)d_out;

    float *adjT, *z, *z2, *qkv;
    cudaGetSymbolAddress((void**)&adjT, g_adjT);
    cudaGetSymbolAddress((void**)&z,    g_z);
    cudaGetSymbolAddress((void**)&z2,   g_z2);
    cudaGetSymbolAddress((void**)&qkv,  g_qkv);

    cudaFuncSetAttribute(vgemm_wmma<0>, cudaFuncAttributeMaxDynamicSharedMemorySize, GSM_TOTAL);
    cudaFuncSetAttribute(vgemm_wmma<1>, cudaFuncAttributeMaxDynamicSharedMemorySize, GSM_TOTAL);
    cudaFuncSetAttribute(vgemm_wmma<2>, cudaFuncAttributeMaxDynamicSharedMemorySize, GSM_TOTAL);

    prep_adj_kernel<<<(V_*V_*LP1_ + 255)/256, 256>>>(adjlog, adjT);
    stage1_kernel<<<M_, 256>>>(x, adjT, var_emb, temp_emb, z);

    dim3 gg(M_/128, V_);
    // mech layers: W strided by NL*H*H per variable (slice li), bias by NL*H
    vgemm_wmma<1><<<gg, 256, GSM_TOTAL>>>(z,  mech_W + 0*H_*H_, mech_b + 0*H_,
                                          nullptr, nullptr, nullptr, nullptr,
                                          ln_g + 0*H_, ln_b + 0*H_, nullptr, nullptr,
                                          z2, NL_*H_*H_, NL_*H_);
    vgemm_wmma<1><<<gg, 256, GSM_TOTAL>>>(z2, mech_W + 1*H_*H_, mech_b + 1*H_,
                                          nullptr, nullptr, nullptr, nullptr,
                                          ln_g + 1*H_, ln_b + 1*H_, nullptr, nullptr,
                                          z,  NL_*H_*H_, NL_*H_);
    vgemm_wmma<1><<<gg, 256, GSM_TOTAL>>>(z,  mech_W + 2*H_*H_, mech_b + 2*H_,
                                          nullptr, nullptr, nullptr, nullptr,
                                          ln_g + 2*H_, ln_b + 2*H_, nullptr, nullptr,
                                          z2, NL_*H_*H_, NL_*H_);
    // fused QKV (grid.z selects weight/bias/output)
    dim3 gq(M_/128, V_, 3);
    vgemm_wmma<0><<<gq, 256, GSM_TOTAL>>>(z2, Wq, bq, Wk, bk, Wv, bv,
                                          nullptr, nullptr, nullptr, nullptr,
                                          qkv, H_*H_, H_);
    // attention -> z (reused as o buffer)
    attn_kernel<<<B_*V_*NH_, 256>>>(qkv, z);
    // O-proj + output head fused
    vgemm_wmma<2><<<gg, 256, GSM_TOTAL>>>(z, Wo, bo, nullptr, nullptr, nullptr, nullptr,
                                          nullptr, nullptr, out_W, out_b, out, H_*H_, H_);
}